// round 7
// baseline (speedup 1.0000x reference)
#include <cuda_runtime.h>

// hidden [4096] f32, encoder_outputs [8192,1,4096] f32
// energies = enc @ hidden -> softmax -> output = enc^T @ attn
// d_out: [0:4096) = output, [4096:12288) = attn
//
// Single pass over enc (read once), online softmax per block, combine kernel
// recomputes global stats per block (no separate finalize launch).

#define SEQ_LEN 8192
#define HIDDEN  4096
#define H4      (HIDDEN / 4)
#define NBLK    1024
#define ROWS_A  (SEQ_LEN / NBLK)    // 8 rows per block
#define BCHUNK  32                  // partials reduced per combine block
#define NBCH    (NBLK / BCHUNK)     // 32

__device__ float g_energies[SEQ_LEN];
__device__ float g_partial[NBLK * HIDDEN];
__device__ float g_m[NBLK];
__device__ float g_l[NBLK];

// ---- Pass 1: fused energies + online-softmax accumulation; zeroes out ----
__global__ __launch_bounds__(256) void pass1(
    const float* __restrict__ enc, const float* __restrict__ hidden,
    float* __restrict__ out)
{
    const int tid  = threadIdx.x;
    const int wid  = tid >> 5;
    const int lane = tid & 31;
    const int r0   = blockIdx.x * ROWS_A;

    if (blockIdx.x < 16) out[blockIdx.x * 256 + tid] = 0.f;

    __shared__ float sm[2][8];

    const float4* h4 = reinterpret_cast<const float4*>(hidden);
    float4 hv0 = h4[tid];
    float4 hv1 = h4[tid + 256];
    float4 hv2 = h4[tid + 512];
    float4 hv3 = h4[tid + 768];

    const float4* base = reinterpret_cast<const float4*>(enc + (size_t)r0 * HIDDEN);

    float4 c0 = base[tid];
    float4 c1 = base[tid + 256];
    float4 c2 = base[tid + 512];
    float4 c3 = base[tid + 768];

    float4 a0 = make_float4(0.f,0.f,0.f,0.f);
    float4 a1 = a0, a2 = a0, a3 = a0;
    float m = -3.4e38f;
    float l = 0.f;

    #pragma unroll 1
    for (int s = 0; s < ROWS_A; ++s) {
        int sn = (s + 1 < ROWS_A) ? s + 1 : s;
        const float4* nb = base + (size_t)sn * H4;
        float4 n0 = nb[tid];
        float4 n1 = nb[tid + 256];
        float4 n2 = nb[tid + 512];
        float4 n3 = nb[tid + 768];

        float part = c0.x*hv0.x + c0.y*hv0.y + c0.z*hv0.z + c0.w*hv0.w
                   + c1.x*hv1.x + c1.y*hv1.y + c1.z*hv1.z + c1.w*hv1.w
                   + c2.x*hv2.x + c2.y*hv2.y + c2.z*hv2.z + c2.w*hv2.w
                   + c3.x*hv3.x + c3.y*hv3.y + c3.z*hv3.z + c3.w*hv3.w;
        #pragma unroll
        for (int off = 16; off > 0; off >>= 1)
            part += __shfl_down_sync(0xFFFFFFFFu, part, off);
        if (lane == 0) sm[s & 1][wid] = part;
        __syncthreads();
        float e = sm[s & 1][0] + sm[s & 1][1] + sm[s & 1][2] + sm[s & 1][3]
                + sm[s & 1][4] + sm[s & 1][5] + sm[s & 1][6] + sm[s & 1][7];
        if (tid == 0) g_energies[r0 + s] = e;

        float mn = fmaxf(m, e);
        float sc = __expf(m - mn);
        float p  = __expf(e - mn);
        a0.x = a0.x*sc + p*c0.x;  a0.y = a0.y*sc + p*c0.y;
        a0.z = a0.z*sc + p*c0.z;  a0.w = a0.w*sc + p*c0.w;
        a1.x = a1.x*sc + p*c1.x;  a1.y = a1.y*sc + p*c1.y;
        a1.z = a1.z*sc + p*c1.z;  a1.w = a1.w*sc + p*c1.w;
        a2.x = a2.x*sc + p*c2.x;  a2.y = a2.y*sc + p*c2.y;
        a2.z = a2.z*sc + p*c2.z;  a2.w = a2.w*sc + p*c2.w;
        a3.x = a3.x*sc + p*c3.x;  a3.y = a3.y*sc + p*c3.y;
        a3.z = a3.z*sc + p*c3.z;  a3.w = a3.w*sc + p*c3.w;
        l = l*sc + p;
        m = mn;

        c0 = n0; c1 = n1; c2 = n2; c3 = n3;
    }

    float4* gp = reinterpret_cast<float4*>(g_partial + (size_t)blockIdx.x * HIDDEN);
    gp[tid]       = a0;
    gp[tid + 256] = a1;
    gp[tid + 512] = a2;
    gp[tid + 768] = a3;
    if (tid == 0) { g_m[blockIdx.x] = m; g_l[blockIdx.x] = l; }
}

// ---- Combine: every block recomputes M,Z from g_m/g_l (L2-hot), then ------
// blocks [0, NBCH*16) accumulate out via atomics; rest write attn.
__global__ __launch_bounds__(256) void combine(
    float* __restrict__ out, float* __restrict__ attn)
{
    __shared__ float red[8];
    __shared__ float sM, sZ;
    const int tid  = threadIdx.x;
    const int wid  = tid >> 5;
    const int lane = tid & 31;

    // global max over NBLK block maxima (4 per thread)
    float m0 = g_m[tid];
    float m1 = g_m[tid + 256];
    float m2 = g_m[tid + 512];
    float m3 = g_m[tid + 768];
    float mv = fmaxf(fmaxf(m0, m1), fmaxf(m2, m3));
    #pragma unroll
    for (int off = 16; off > 0; off >>= 1)
        mv = fmaxf(mv, __shfl_xor_sync(0xFFFFFFFFu, mv, off));
    if (lane == 0) red[wid] = mv;
    __syncthreads();
    if (tid == 0) {
        float v = red[0];
        #pragma unroll
        for (int i = 1; i < 8; ++i) v = fmaxf(v, red[i]);
        sM = v;
    }
    __syncthreads();
    float M = sM;

    // Z = sum_b l_b * exp(m_b - M)
    float zt = g_l[tid]       * __expf(m0 - M)
             + g_l[tid + 256] * __expf(m1 - M)
             + g_l[tid + 512] * __expf(m2 - M)
             + g_l[tid + 768] * __expf(m3 - M);
    #pragma unroll
    for (int off = 16; off > 0; off >>= 1)
        zt += __shfl_xor_sync(0xFFFFFFFFu, zt, off);
    if (lane == 0) red[wid] = zt;
    __syncthreads();
    if (tid == 0) {
        float v = red[0];
        #pragma unroll
        for (int i = 1; i < 8; ++i) v += red[i];
        sZ = v;
    }
    __syncthreads();
    float invZ = 1.0f / sZ;

    const int gid = blockIdx.x;
    if (gid < NBCH * 16) {
        const int col = (gid & 15) * 256 + tid;
        const int b0  = (gid >> 4) * BCHUNK;
        float acc = 0.f;
        #pragma unroll 8
        for (int b = b0; b < b0 + BCHUNK; ++b)
            acc += g_partial[(size_t)b * HIDDEN + col] * (__expf(g_m[b] - M) * invZ);
        atomicAdd(&out[col], acc);
    } else {
        const int i = (gid - NBCH * 16) * 256 + tid;
        attn[i] = __expf(g_energies[i] - M) * invZ;
    }
}

extern "C" void kernel_launch(void* const* d_in, const int* in_sizes, int n_in,
                              void* d_out, int out_size)
{
    const float* hidden = (const float*)d_in[0];
    const float* enc    = (const float*)d_in[1];
    float* out  = (float*)d_out;
    float* attn = (float*)d_out + HIDDEN;

    pass1<<<NBLK, 256>>>(enc, hidden, out);
    combine<<<NBCH * 16 + SEQ_LEN / 256, 256>>>(out, attn);
}